// round 5
// baseline (speedup 1.0000x reference)
#include <cuda_runtime.h>
#include <math.h>

#define NN 4096
#define MAXSEG 512
#define GCELLS 1024
#define FULLM 0xffffffffu
#define SENT 1e38f

__device__ __forceinline__ float warp_sum(float v) {
    #pragma unroll
    for (int o = 8; o; o >>= 1) v += __shfl_xor_sync(FULLM, v, o);  // lanes 16+ hold 0
    return v;                                                       // lane 0 has sum(0..15)
}
__device__ __forceinline__ float warp_min32(float v) {
    #pragma unroll
    for (int o = 16; o; o >>= 1) v = fminf(v, __shfl_xor_sync(FULLM, v, o));
    return v;
}

__global__ void __launch_bounds__(256, 4) ode_fused(
    const float* __restrict__ x,   const float* __restrict__ A,
    const float* __restrict__ WA0, const float* __restrict__ bA0,
    const float* __restrict__ WA1, const float* __restrict__ bA1,
    const float* __restrict__ WA2, const float* __restrict__ bA2,
    const float* __restrict__ Wm0, const float* __restrict__ bm0,
    const float* __restrict__ Wm1, const float* __restrict__ bm1,
    const float* __restrict__ wA,  const float* __restrict__ wf,
    float* __restrict__ out)
{
    __shared__ float  sW1T[256];           // [k][l] = WA1[l][k]
    __shared__ float  sT[16];
    __shared__ int    sK[16];
    __shared__ float  sB[MAXSEG + 1];
    __shared__ float2 scd[MAXSEG];
    __shared__ float2 lutcd[GCELLS];
    __shared__ float  red[256];
    __shared__ int    sCnt, sP;

    const int i   = blockIdx.x;
    const int tid = threadIdx.x;
    const int lane = tid & 31;
    const float* __restrict__ Arow = A + (size_t)i * NN;

    // prefetch this thread's A elements (overlaps the build below)
    float4 a4[4];
    #pragma unroll
    for (int q = 0; q < 4; q++)
        a4[q] = *reinterpret_cast<const float4*>(Arow + (q * 256 + tid) * 4);

    sW1T[tid] = WA1[(tid & 15) * 16 + (tid >> 4)];   // transpose: [k][l]

    // ---------------- warp 0: build exact PWL segment table into smem ----------------
    if (tid < 32) {
        const float xi = x[i];
        float u = 0.f, v = 0.f, w2 = 0.f, b1l = 0.f;
        if (lane < 16) {
            u   = fmaf(WA0[2 * lane], xi, bA0[lane]);
            v   = WA0[2 * lane + 1];
            w2  = WA2[lane];
            b1l = bA1[lane];
        }
        __syncwarp();   // sW1T rows for k written by lanes of this warp are visible;
                        // (warp 0 wrote k=0,1 rows; full table synced at block barrier —
                        //  so read W1 via shuffles instead of sW1T here)
        // W1 column access via per-lane register copy (lane l holds W1[l][*]):
        float w1l[16];
        #pragma unroll
        for (int k = 0; k < 16; k++)
            w1l[k] = (lane < 16) ? WA1[lane * 16 + k] : 0.f;

        // layer-0 knots, rank-sorted, with owner
        const bool tv = (lane < 16) && (fabsf(v) > 1e-30f);
        const float tk = tv ? (-u / v) : 3e30f;
        int rank = 0;
        #pragma unroll
        for (int k = 0; k < 16; k++) {
            float o = __shfl_sync(FULLM, tk, k);
            rank += (o < tk) || (o == tk && k < lane);
        }
        const int nk = __popc(__ballot_sync(FULLM, tv) & 0xffffu);
        if (tv) { sT[rank] = tk; sK[rank] = lane; }
        __syncwarp();

        // active set at x -> -inf
        const unsigned actmask =
            __ballot_sync(FULLM, (lane < 16) && ((v < 0.f) || (v == 0.f && u > 0.f)));

        float al = b1l, be = 0.f;
        #pragma unroll
        for (int k = 0; k < 16; k++) {
            const float uk = __shfl_sync(FULLM, u, k);
            const float vk = __shfl_sync(FULLM, v, k);
            if (actmask & (1u << k)) {
                al = fmaf(w1l[k], uk, al);
                be = fmaf(w1l[k], vk, be);
            }
        }
        if (lane >= 16) { al = 0.f; be = 0.f; }

        const float cbase = fmaf(wA[0], xi, bA2[0]);
        const float dbase = wA[1];

        int cnt = 0;
        for (int s0 = 0; s0 <= nk; s0++) {
            if (s0 > 0) {                       // flip knot just crossed
                const int kst = sK[s0 - 1];
                const float uk = __shfl_sync(FULLM, u, kst);
                const float vk = __shfl_sync(FULLM, v, kst);
                if (lane < 16) {
                    const float sw = (vk > 0.f) ? w1l[kst] : -w1l[kst];
                    al = fmaf(sw, uk, al);
                    be = fmaf(sw, vk, be);
                }
            }
            const float lo = (s0 == 0)  ? -1e30f : sT[s0 - 1];
            const float hi = (s0 == nk) ?  1e30f : sT[s0];
            if (!(hi > lo)) continue;

            const float z = -al / be;
            bool zv = (lane < 16) && (fabsf(be) > 1e-30f) && (z > lo) && (z < hi);

            float cur = lo;
            while (true) {
                const float zc = zv ? z : 3e30f;
                const float b  = fminf(warp_min32(zc), hi);
                const float m2 = 0.5f * cur + 0.5f * b;
                const bool sgn = (lane < 16) && (fmaf(be, m2, al) > 0.f);
                float cc = warp_sum(sgn ? w2 * al : 0.f);
                float dd = warp_sum(sgn ? w2 * be : 0.f);
                if (lane == 0) {
                    sB[cnt]  = (cnt == 0) ? -1e38f : cur;
                    scd[cnt] = make_float2(cbase + cc, dbase + dd);
                }
                cnt++;
                if (!(b < hi)) break;
                if (zv && z <= b) zv = false;
                cur = b;
            }
        }

        int P = 1; while (P < cnt) P <<= 1;
        for (int s = cnt + lane; s <= P; s += 32) sB[s] = 3e38f;  // pad incl. sB[P]
        if (lane == 0) { sCnt = cnt; sP = P; }
    }
    __syncthreads();

    // ---------------- all warps: per-cell (c,d) LUT with straddle sentinel ----------------
    const int P = sP;
    for (int g = tid; g < GCELLS; g += 256) {
        const float xl = (g == 0) ? -3e38f : fmaf((float)g, 1.0f / 64.0f, -8.0f);
        const float xr = (g == GCELLS - 1) ? 3e38f : fmaf((float)(g + 1), 1.0f / 64.0f, -8.0f);
        int pos = 0;
        for (int st = P >> 1; st; st >>= 1)
            if (sB[pos + st] <= xl) pos += st;
        const bool straddle = (sB[pos + 1] < xr);
        lutcd[g] = straddle ? make_float2(0.f, SENT) : scd[pos];
    }
    __syncthreads();

    // ---------------- apply: one LDS.64 per element on the hot path ----------------
    float acc = 0.f;
    #pragma unroll
    for (int q = 0; q < 4; q++) {
        const int j = (q * 256 + tid) * 4;
        const float4 x4 = *reinterpret_cast<const float4*>(x + j);
        const float xa[4] = {x4.x, x4.y, x4.z, x4.w};
        const float aa[4] = {a4[q].x, a4[q].y, a4[q].z, a4[q].w};
        #pragma unroll
        for (int e = 0; e < 4; e++) {
            const float xj = xa[e];
            int idx = __float2int_rd(fmaf(xj, 64.f, 512.f));
            idx = min(max(idx, 0), GCELLS - 1);
            float2 cd = lutcd[idx];
            if (cd.y == SENT) {                     // rare exact fallback
                int pos = 0;
                for (int st = P >> 1; st; st >>= 1)
                    if (sB[pos + st] <= xj) pos += st;
                cd = scd[pos];
            }
            acc = fmaf(aa[e], fmaf(cd.y, xj, cd.x), acc);
        }
    }

    red[tid] = acc;
    __syncthreads();
    #pragma unroll
    for (int s = 128; s; s >>= 1) {
        if (tid < s) red[tid] += red[tid + s];
        __syncthreads();
    }
    if (tid == 0) {
        const float xi = x[i];
        float xn = fmaf(wf[0], xi, bm1[0]);
        #pragma unroll
        for (int k = 0; k < 16; k++)
            xn = fmaf(Wm1[k], fmaxf(fmaf(Wm0[k], xi, bm0[k]), 0.f), xn);
        out[i] = xn + red[0];
    }
}

extern "C" void kernel_launch(void* const* d_in, const int* in_sizes, int n_in,
                              void* d_out, int out_size) {
    // input order: t, x, A, WA0, bA0, WA1, bA1, WA2, bA2, Wm0, bm0, Wm1, bm1, wA, wf
    const float* x   = (const float*)d_in[1];
    const float* A   = (const float*)d_in[2];
    const float* WA0 = (const float*)d_in[3];
    const float* bA0 = (const float*)d_in[4];
    const float* WA1 = (const float*)d_in[5];
    const float* bA1 = (const float*)d_in[6];
    const float* WA2 = (const float*)d_in[7];
    const float* bA2 = (const float*)d_in[8];
    const float* Wm0 = (const float*)d_in[9];
    const float* bm0 = (const float*)d_in[10];
    const float* Wm1 = (const float*)d_in[11];
    const float* bm1 = (const float*)d_in[12];
    const float* wA  = (const float*)d_in[13];
    const float* wf  = (const float*)d_in[14];
    float* out = (float*)d_out;

    ode_fused<<<NN, 256>>>(x, A, WA0, bA0, WA1, bA1, WA2, bA2,
                           Wm0, bm0, Wm1, bm1, wA, wf, out);
}

// round 6
// speedup vs baseline: 2.5360x; 2.5360x over previous
#include <cuda_runtime.h>
#include <math.h>

#define NN 4096
#define MAXSEG 512
#define GCELLS 1024
#define FULLM 0xffffffffu
#define SENT 1e38f

// scratch tables per row i (static device memory — no allocs)
__device__ float g_B[NN * MAXSEG];
__device__ float g_c[NN * MAXSEG];
__device__ float g_d[NN * MAXSEG];
__device__ int   g_cnt[NN];

// ---------------- build: one warp per row, mirrored halves ----------------
__global__ void __launch_bounds__(256) build_pwl(
    const float* __restrict__ x,
    const float* __restrict__ WA0, const float* __restrict__ bA0,
    const float* __restrict__ WA1, const float* __restrict__ bA1,
    const float* __restrict__ WA2, const float* __restrict__ bA2,
    const float* __restrict__ wA)
{
    __shared__ float sT[8][16];
    __shared__ int   sK[8][16];
    const int warp = threadIdx.x >> 5, lane = threadIdx.x & 31;
    const int ll = lane & 15;                 // mirrored lane id
    const int i = blockIdx.x * 8 + warp;
    const float xi = x[i];

    // every lane (both halves) holds unit ll's affine data
    const float u   = fmaf(WA0[2 * ll], xi, bA0[ll]);
    const float v   = WA0[2 * ll + 1];
    const float w2  = WA2[ll];
    const float b1l = bA1[ll];
    float w1l[16];
    #pragma unroll
    for (int k = 0; k < 16; k++) w1l[k] = WA1[ll * 16 + k];

    // layer-0 knots (lanes<16 own them), rank-sorted with owner
    const bool tv = (lane < 16) && (fabsf(v) > 1e-30f);
    const float tk = tv ? (-u / v) : 3e30f;
    int rank = 0;
    #pragma unroll
    for (int k = 0; k < 16; k++) {
        float o = __shfl_sync(FULLM, tk, k);
        rank += (o < tk) || (o == tk && k < lane);
    }
    const int nk = __popc(__ballot_sync(FULLM, tv) & 0xffffu);
    if (tv) { sT[warp][rank] = tk; sK[warp][rank] = lane; }
    __syncwarp();

    // active set at x -> -inf (mirrored ballot; use low 16 bits)
    const unsigned actmask =
        __ballot_sync(FULLM, (v < 0.f) || (v == 0.f && u > 0.f)) & 0xffffu;

    float al = b1l, be = 0.f;                 // identical in both halves
    #pragma unroll
    for (int k = 0; k < 16; k++) {
        const float uk = __shfl_sync(FULLM, u, k);
        const float vk = __shfl_sync(FULLM, v, k);
        if (actmask & (1u << k)) {
            al = fmaf(w1l[k], uk, al);
            be = fmaf(w1l[k], vk, be);
        }
    }

    const float cbase = fmaf(wA[0], xi, bA2[0]);
    const float dbase = wA[1];

    int cnt = 0;
    for (int s0 = 0; s0 <= nk; s0++) {
        if (s0 > 0) {                         // flip knot just crossed (all lanes)
            const int kst = sK[warp][s0 - 1];
            const float uk = __shfl_sync(FULLM, u, kst);
            const float vk = __shfl_sync(FULLM, v, kst);
            const float sw = (vk > 0.f) ? w1l[kst] : -w1l[kst];
            al = fmaf(sw, uk, al);
            be = fmaf(sw, vk, be);
        }
        const float lo = (s0 == 0)  ? -1e30f : sT[warp][s0 - 1];
        const float hi = (s0 == nk) ?  1e30f : sT[warp][s0];
        if (!(hi > lo)) continue;

        const float z = -al / be;
        bool zv = (fabsf(be) > 1e-30f) && (z > lo) && (z < hi);  // mirrored

        float cur = lo;
        while (true) {
            // half-local min (both halves identical) -> 4 shuffles
            float zc = zv ? z : 3e30f;
            #pragma unroll
            for (int o = 8; o; o >>= 1) zc = fminf(zc, __shfl_xor_sync(FULLM, zc, o));
            const float b  = fminf(zc, hi);
            const float m2 = 0.5f * cur + 0.5f * b;
            const bool sgn = fmaf(be, m2, al) > 0.f;
            // lanes 0-15 reduce w2*al (cc), lanes 16-31 reduce w2*be (dd): 4 shuffles
            float contrib = sgn ? ((lane < 16) ? w2 * al : w2 * be) : 0.f;
            #pragma unroll
            for (int o = 8; o; o >>= 1) contrib += __shfl_xor_sync(FULLM, contrib, o);
            const float ddv = __shfl_sync(FULLM, contrib, 16);
            if (lane == 0) {
                g_B[i * MAXSEG + cnt] = (cnt == 0) ? -1e38f : cur;
                g_c[i * MAXSEG + cnt] = cbase + contrib;
                g_d[i * MAXSEG + cnt] = dbase + ddv;
            }
            cnt++;
            if (!(b < hi)) break;
            if (zv && z <= b) zv = false;
            cur = b;
        }
    }
    if (lane == 0) g_cnt[i] = cnt;
}

// ---------------- apply: one CTA per row ----------------
__global__ void __launch_bounds__(256) pwl_apply(
    const float* __restrict__ x, const float* __restrict__ A,
    const float* __restrict__ Wm0, const float* __restrict__ bm0,
    const float* __restrict__ Wm1, const float* __restrict__ bm1,
    const float* __restrict__ wf,
    float* __restrict__ out)
{
    __shared__ float  sB[MAXSEG + 1];
    __shared__ float2 scd[MAXSEG];
    __shared__ float2 lutcd[GCELLS];
    __shared__ float  redw[8];
    const int i = blockIdx.x, tid = threadIdx.x;
    const float* __restrict__ Arow = A + (size_t)i * NN;

    // prefetch this thread's A elements (hides DRAM behind LUT build)
    float4 a4[4];
    #pragma unroll
    for (int q = 0; q < 4; q++)
        a4[q] = *reinterpret_cast<const float4*>(Arow + (q * 256 + tid) * 4);

    const int cnt = g_cnt[i];
    int P = 1; while (P < cnt) P <<= 1;

    for (int s = tid; s <= P; s += 256) {
        sB[s] = (s < cnt) ? g_B[i * MAXSEG + s] : 3e38f;
        if (s < cnt) scd[s] = make_float2(g_c[i * MAXSEG + s], g_d[i * MAXSEG + s]);
    }
    __syncthreads();

    // per-cell (c,d) LUT; straddle cells carry (start_pos, SENT)
    for (int g = tid; g < GCELLS; g += 256) {
        const float xl = (g == 0) ? -3e38f : fmaf((float)g, 1.0f / 64.0f, -8.0f);
        const float xr = (g == GCELLS - 1) ? 3e38f
                                           : fmaf((float)(g + 1), 1.0f / 64.0f, -8.0f);
        int pos = 0;
        for (int st = P >> 1; st; st >>= 1)
            if (sB[pos + st] <= xl) pos += st;
        lutcd[g] = (sB[pos + 1] < xr) ? make_float2(__int_as_float(pos), SENT)
                                      : scd[pos];
    }
    __syncthreads();

    float acc = 0.f;
    #pragma unroll
    for (int q = 0; q < 4; q++) {
        const int j = (q * 256 + tid) * 4;
        const float4 x4 = *reinterpret_cast<const float4*>(x + j);
        const float xa[4] = {x4.x, x4.y, x4.z, x4.w};
        const float aa[4] = {a4[q].x, a4[q].y, a4[q].z, a4[q].w};
        #pragma unroll
        for (int e = 0; e < 4; e++) {
            const float xj = xa[e];
            int idx = __float2int_rd(fmaf(xj, 64.f, 512.f));
            idx = min(max(idx, 0), GCELLS - 1);
            float2 cd = lutcd[idx];
            if (cd.y == SENT) {                 // short walk from stored pos
                int pos = __float_as_int(cd.x);
                while (sB[pos + 1] <= xj) pos++;
                cd = scd[pos];
            }
            acc = fmaf(aa[e], fmaf(cd.y, xj, cd.x), acc);
        }
    }

    // warp-shuffle reduce, then cross-warp via smem
    #pragma unroll
    for (int o = 16; o; o >>= 1) acc += __shfl_xor_sync(FULLM, acc, o);
    if ((tid & 31) == 0) redw[tid >> 5] = acc;
    __syncthreads();
    if (tid == 0) {
        float xA = 0.f;
        #pragma unroll
        for (int w = 0; w < 8; w++) xA += redw[w];
        const float xi = x[i];
        float xn = fmaf(wf[0], xi, bm1[0]);
        #pragma unroll
        for (int k = 0; k < 16; k++)
            xn = fmaf(Wm1[k], fmaxf(fmaf(Wm0[k], xi, bm0[k]), 0.f), xn);
        out[i] = xn + xA;
    }
}

extern "C" void kernel_launch(void* const* d_in, const int* in_sizes, int n_in,
                              void* d_out, int out_size) {
    // input order: t, x, A, WA0, bA0, WA1, bA1, WA2, bA2, Wm0, bm0, Wm1, bm1, wA, wf
    const float* x   = (const float*)d_in[1];
    const float* A   = (const float*)d_in[2];
    const float* WA0 = (const float*)d_in[3];
    const float* bA0 = (const float*)d_in[4];
    const float* WA1 = (const float*)d_in[5];
    const float* bA1 = (const float*)d_in[6];
    const float* WA2 = (const float*)d_in[7];
    const float* bA2 = (const float*)d_in[8];
    const float* Wm0 = (const float*)d_in[9];
    const float* bm0 = (const float*)d_in[10];
    const float* Wm1 = (const float*)d_in[11];
    const float* bm1 = (const float*)d_in[12];
    const float* wA  = (const float*)d_in[13];
    const float* wf  = (const float*)d_in[14];
    float* out = (float*)d_out;

    build_pwl<<<NN / 8, 256>>>(x, WA0, bA0, WA1, bA1, WA2, bA2, wA);
    pwl_apply<<<NN, 256>>>(x, A, Wm0, bm0, Wm1, bm1, wf, out);
}